// round 11
// baseline (speedup 1.0000x reference)
#include <cuda_runtime.h>
#include <cstdint>
#include <cstddef>

// GroupedLinearsAdvanced: out[b,o,d] = sum_i x[b,i,d] * W[d,i,o] + bias[d,o]
//   x:    [16, 128, 4096] fp32
//   W:    [4096, 128, 128] fp32   (256 MB, streamed once -> HBM bound)
//   bias: [4096, 128] fp32
//   out:  [16, 128, 4096] fp32
//
// R8 (third submission; two prior GB300 container failures were infra, not
// kernel): b-split warp pairs. Two warps per d-channel (warp h owns batches
// 8h..8h+7) -> accumulators halve to 32 regs -> ~78 regs total -> 3 CTAs
// x 256 thr = 24 warps/SM (6/SMSP) for latency hiding. W loads stay full
// LDG.128; the twin warp's identical addresses dedup in L2, so W DRAM
// traffic is unchanged. x LDS is split (not duplicated). 4-deep register
// W ring retained.

#define B_SZ     16
#define IN_D     128
#define OUT_D    128
#define D_TOT    4096
#define D_TILE   4
#define THREADS  256
#define PF_DEPTH 4
#define XS_STRIDE 72                       // floats per i-row: 4*16 + 8 pad
#define SMEM_FLOATS (IN_D * XS_STRIDE)     // 9216 floats = 36864 B
#define SMEM_BYTES  (SMEM_FLOATS * 4)

__global__ void __launch_bounds__(THREADS, 3)
grouped_linears_kernel(const float* __restrict__ x,
                       const float* __restrict__ W,
                       const float* __restrict__ bias,
                       float* __restrict__ out)
{
    extern __shared__ float sm[];   // phase 1: x tile   phase 2: out transpose

    const int tid   = threadIdx.x;
    const int warp  = tid >> 5;        // 0..7
    const int lane  = tid & 31;
    const int dd    = warp >> 1;       // d-channel within tile: 0..3
    const int bbase = 8 * (warp & 1);  // this warp's first batch: 0 or 8
    const int d0    = blockIdx.x * D_TILE;
    const int d     = d0 + dd;

    // W[d][i][4*lane] as float4; each i advances 128 floats = 32 float4.
    // Twin warps (same dd) issue identical addresses -> L2 dedups; DRAM
    // reads each line once. Plain loads (default policy) keep the line
    // resident for its single reuse.
    const float4* wp = reinterpret_cast<const float4*>(W + (size_t)d * IN_D * OUT_D) + lane;
    float4 wbuf[PF_DEPTH];
#pragma unroll
    for (int s = 0; s < PF_DEPTH; ++s) wbuf[s] = wp[s * 32];

    // bias early too
    float4 bv = *reinterpret_cast<const float4*>(bias + (size_t)d * OUT_D + 4 * lane);

    // ---------------- Phase 0: load x tile ----------------
    // sm[i*XS_STRIDE + c*16 + b] = x[b][i][d0+c]; 8 float4 per thread.
#pragma unroll
    for (int r = 0; r < 8; ++r) {
        int p = tid + r * THREADS;      // 0..2047
        int i = p >> 4;
        int b = p & 15;
        float4 v = *reinterpret_cast<const float4*>(
            x + ((size_t)b * IN_D + i) * D_TOT + d0);
        float* row = &sm[i * XS_STRIDE + b];
        row[0 * 16] = v.x; row[1 * 16] = v.y; row[2 * 16] = v.z; row[3 * 16] = v.w;
    }
    __syncthreads();

    // ---------------- Phase 1: main GEMM loop ----------------
    // acc2[k][j]: packed f32x2 accumulator for (b=bbase+2k lo, +2k+1 hi),
    // o = 4*lane + j.
    unsigned long long acc2[4][4];
    {
        float bj[4] = {bv.x, bv.y, bv.z, bv.w};
#pragma unroll
        for (int j = 0; j < 4; ++j) {
            unsigned long long pk;
            asm("mov.b64 %0, {%1, %1};" : "=l"(pk) : "f"(bj[j]));
#pragma unroll
            for (int k = 0; k < 4; ++k) acc2[k][j] = pk;
        }
    }

#pragma unroll 4
    for (int i = 0; i < IN_D; ++i) {
        // consume slot, immediately re-fill it PF_DEPTH iterations ahead
        float4 wcur = wbuf[i & (PF_DEPTH - 1)];
        int ipf = i + PF_DEPTH;
        if (ipf < IN_D) wbuf[i & (PF_DEPTH - 1)] = wp[ipf * 32];

        // x pairs for this (i, d, b-half): 8 floats = 2x LDS.128 broadcast
        const double2* xr =
            reinterpret_cast<const double2*>(&sm[i * XS_STRIDE + dd * 16 + bbase]);
        double2 a0 = xr[0], a1 = xr[1];
        unsigned long long x2[4];
        x2[0] = __double_as_longlong(a0.x); x2[1] = __double_as_longlong(a0.y);
        x2[2] = __double_as_longlong(a1.x); x2[3] = __double_as_longlong(a1.y);

        // duplicate W scalars into both f32x2 halves
        unsigned long long wd[4];
        asm("mov.b64 %0, {%1, %1};" : "=l"(wd[0]) : "f"(wcur.x));
        asm("mov.b64 %0, {%1, %1};" : "=l"(wd[1]) : "f"(wcur.y));
        asm("mov.b64 %0, {%1, %1};" : "=l"(wd[2]) : "f"(wcur.z));
        asm("mov.b64 %0, {%1, %1};" : "=l"(wd[3]) : "f"(wcur.w));

#pragma unroll
        for (int k = 0; k < 4; ++k) {
#pragma unroll
            for (int j = 0; j < 4; ++j) {
                asm("fma.rn.f32x2 %0, %1, %2, %0;"
                    : "+l"(acc2[k][j]) : "l"(x2[k]), "l"(wd[j]));
            }
        }
    }

    // ---------------- Phase 2: transpose through smem ----------------
    __syncthreads();   // done reading x tile
    // outs[c][b*128 + o], c = dd; this warp writes b = bbase..bbase+7.
    float* outs = sm;
#pragma unroll
    for (int k = 0; k < 4; ++k) {
#pragma unroll
        for (int j = 0; j < 4; ++j) {
            float lo, hi;
            asm("mov.b64 {%0, %1}, %2;" : "=f"(lo), "=f"(hi) : "l"(acc2[k][j]));
            int o = 4 * lane + j;
            outs[dd * 2048 + (bbase + 2 * k)     * 128 + o] = lo;
            outs[dd * 2048 + (bbase + 2 * k + 1) * 128 + o] = hi;
        }
    }
    __syncthreads();

    // ---------------- Phase 3: coalesced global store ----------------
    // Each (b,o) pair p gets a 4-float d-contiguous run (one float4; the
    // adjacent-d0 CTA fills the sector's other half, merged in L2).
#pragma unroll
    for (int r = 0; r < 2; ++r) {
        int p4 = 4 * (tid + r * THREADS);   // groups of 4 consecutive p
        float v[D_TILE][4];
#pragma unroll
        for (int c = 0; c < D_TILE; ++c) {
            float4 t4 = *reinterpret_cast<float4*>(&outs[c * 2048 + p4]);
            v[c][0] = t4.x; v[c][1] = t4.y; v[c][2] = t4.z; v[c][3] = t4.w;
        }
#pragma unroll
        for (int pp = 0; pp < 4; ++pp) {
            int p = p4 + pp;            // p = b*128 + o
            float* op = out + (size_t)p * D_TOT + d0;
            *reinterpret_cast<float4*>(op) =
                make_float4(v[0][pp], v[1][pp], v[2][pp], v[3][pp]);
        }
    }
}

extern "C" void kernel_launch(void* const* d_in, const int* in_sizes, int n_in,
                              void* d_out, int out_size)
{
    (void)in_sizes; (void)n_in; (void)out_size;
    const float* x    = (const float*)d_in[0];
    const float* W    = (const float*)d_in[1];
    const float* bias = (const float*)d_in[2];
    float*       out  = (float*)d_out;

    // Idempotent, host-side, not a stream op: safe under graph capture.
    cudaFuncSetAttribute(grouped_linears_kernel,
                         cudaFuncAttributeMaxDynamicSharedMemorySize, SMEM_BYTES);

    grouped_linears_kernel<<<D_TOT / D_TILE, THREADS, SMEM_BYTES>>>(x, W, bias, out);
}

// round 12
// speedup vs baseline: 1.0934x; 1.0934x over previous
#include <cuda_runtime.h>
#include <cstdint>
#include <cstddef>

// GroupedLinearsAdvanced: out[b,o,d] = sum_i x[b,i,d] * W[d,i,o] + bias[d,o]
//   x:    [16, 128, 4096] fp32
//   W:    [4096, 128, 128] fp32   (256 MB, streamed once -> HBM bound)
//   bias: [4096, 128] fp32
//   out:  [16, 128, 4096] fp32
//
// R11: W stream moved from per-warp LDG (measured ceiling: DRAM 37-46%
// across 5 variants) to cp.async.bulk (TMA engine). Each warp owns a
// 2-stage x 8KB smem ring + mbarriers; lane 0 issues an 8KB bulk copy per
// 16-i chunk, 2 chunks ahead. 64KB/SM in flight through the TMA path, no
// LSU/MLP cap. Inner f32x2 loop, x tile, and output transpose are R5's
// (best CUDA-core variant, fp32-exact).

#define B_SZ     16
#define IN_D     128
#define OUT_D    128
#define D_TOT    4096
#define D_TILE   4
#define THREADS  128
#define CHUNK_I  16
#define NCHUNK   (IN_D / CHUNK_I)          // 8
#define NSTAGE   2
#define WCHUNK_BYTES (CHUNK_I * OUT_D * 4) // 8192
#define XS_STRIDE 72                       // floats per i-row: 4*16 + 8 pad
#define X_BYTES   (IN_D * XS_STRIDE * 4)   // 36864
#define MBAR_OFF  X_BYTES                  // 8 mbarriers (4 warps x 2)
#define WRING_OFF 37888                    // 1024-aligned
#define SMEM_BYTES (WRING_OFF + D_TILE * NSTAGE * WCHUNK_BYTES)  // 103424

__device__ __forceinline__ void mbar_init(uint32_t a, uint32_t cnt) {
    asm volatile("mbarrier.init.shared.b64 [%0], %1;" :: "r"(a), "r"(cnt) : "memory");
}
__device__ __forceinline__ void mbar_expect_tx(uint32_t a, uint32_t bytes) {
    asm volatile("mbarrier.arrive.expect_tx.shared.b64 _, [%0], %1;"
                 :: "r"(a), "r"(bytes) : "memory");
}
__device__ __forceinline__ void mbar_wait(uint32_t a, uint32_t parity) {
    asm volatile(
        "{\n\t.reg .pred P1;\n\t"
        "WAIT_%=:\n\t"
        "mbarrier.try_wait.parity.acquire.cta.shared::cta.b64 P1, [%0], %1, 0x989680;\n\t"
        "@P1 bra.uni DONE_%=;\n\t"
        "bra.uni WAIT_%=;\n\t"
        "DONE_%=:\n\t}"
        :: "r"(a), "r"(parity) : "memory");
}
__device__ __forceinline__ void bulk_g2s(uint32_t dst, const void* src,
                                         uint32_t bytes, uint32_t mbar) {
    asm volatile(
        "cp.async.bulk.shared::cluster.global.mbarrier::complete_tx::bytes "
        "[%0], [%1], %2, [%3];"
        :: "r"(dst), "l"(src), "r"(bytes), "r"(mbar) : "memory");
}

__global__ void __launch_bounds__(THREADS, 2)
grouped_linears_kernel(const float* __restrict__ x,
                       const float* __restrict__ W,
                       const float* __restrict__ bias,
                       float* __restrict__ out)
{
    extern __shared__ __align__(1024) char smraw[];
    float* sm = reinterpret_cast<float*>(smraw);   // x tile / out transpose

    const int tid  = threadIdx.x;
    const int warp = tid >> 5;      // 0..3, one d-channel per warp
    const int lane = tid & 31;
    const int d0   = blockIdx.x * D_TILE;
    const int d    = d0 + warp;

    const uint32_t sbase = (uint32_t)__cvta_generic_to_shared(smraw);
    const uint32_t mbar0 = sbase + MBAR_OFF + (uint32_t)warp * NSTAGE * 8;
    const uint32_t wring = sbase + WRING_OFF + (uint32_t)warp * NSTAGE * WCHUNK_BYTES;
    const char*    wg    = reinterpret_cast<const char*>(W + (size_t)d * IN_D * OUT_D);

    // ---------------- mbarrier init ----------------
    if (tid == 0) {
#pragma unroll
        for (int m = 0; m < D_TILE * NSTAGE; ++m)
            mbar_init(sbase + MBAR_OFF + m * 8, 1);
    }
    __syncthreads();    // mbarriers visible to all warps before any TMA

    // ---------------- prologue: launch first 2 W chunks per warp ----------------
    if (lane == 0) {
#pragma unroll
        for (int s = 0; s < NSTAGE; ++s) {
            mbar_expect_tx(mbar0 + s * 8, WCHUNK_BYTES);
            bulk_g2s(wring + s * WCHUNK_BYTES, wg + s * WCHUNK_BYTES,
                     WCHUNK_BYTES, mbar0 + s * 8);
        }
    }

    // bias early
    float4 bv = *reinterpret_cast<const float4*>(bias + (size_t)d * OUT_D + 4 * lane);

    // ---------------- Phase 0: load x tile ----------------
    // sm[i*XS_STRIDE + c*16 + b] = x[b][i][d0+c]; 16 float4 per thread.
#pragma unroll
    for (int r = 0; r < 16; ++r) {
        int p = tid + r * THREADS;      // 0..2047
        int i = p >> 4;
        int b = p & 15;
        float4 v = *reinterpret_cast<const float4*>(
            x + ((size_t)b * IN_D + i) * D_TOT + d0);
        float* row = &sm[i * XS_STRIDE + b];
        row[0 * 16] = v.x; row[1 * 16] = v.y; row[2 * 16] = v.z; row[3 * 16] = v.w;
    }
    __syncthreads();

    // ---------------- Phase 1: main GEMM loop ----------------
    // acc2[k][j]: packed f32x2 accumulator for (b=2k lo, b=2k+1 hi), o = 4*lane + j.
    unsigned long long acc2[8][4];
    {
        float bj[4] = {bv.x, bv.y, bv.z, bv.w};
#pragma unroll
        for (int j = 0; j < 4; ++j) {
            unsigned long long pk;
            asm("mov.b64 %0, {%1, %1};" : "=l"(pk) : "f"(bj[j]));
#pragma unroll
            for (int k = 0; k < 8; ++k) acc2[k][j] = pk;
        }
    }

    const float* wsm_base = reinterpret_cast<const float*>(smraw + WRING_OFF) +
                            warp * NSTAGE * (WCHUNK_BYTES / 4);

    for (int c = 0; c < NCHUNK; ++c) {
        const int s  = c & 1;
        const int ph = (c >> 1) & 1;    // slot s sees phases 0,1,0,1 over its 4 uses
        mbar_wait(mbar0 + s * 8, (uint32_t)ph);

        const float* wsm = wsm_base + s * (WCHUNK_BYTES / 4);

#pragma unroll
        for (int ii = 0; ii < CHUNK_I; ++ii) {
            const int i = c * CHUNK_I + ii;

            // W for this (i, d, lane): conflict-free LDS.128 (128B phase groups)
            float4 wcur = *reinterpret_cast<const float4*>(wsm + ii * OUT_D + 4 * lane);

            // x pairs for this (i, d): 16 floats = 4x LDS.128, all lanes broadcast
            const double2* xr =
                reinterpret_cast<const double2*>(&sm[i * XS_STRIDE + warp * 16]);
            double2 a0 = xr[0], a1 = xr[1], a2 = xr[2], a3 = xr[3];
            unsigned long long x2[8];
            x2[0] = __double_as_longlong(a0.x); x2[1] = __double_as_longlong(a0.y);
            x2[2] = __double_as_longlong(a1.x); x2[3] = __double_as_longlong(a1.y);
            x2[4] = __double_as_longlong(a2.x); x2[5] = __double_as_longlong(a2.y);
            x2[6] = __double_as_longlong(a3.x); x2[7] = __double_as_longlong(a3.y);

            // duplicate W scalars into both f32x2 halves
            unsigned long long wd[4];
            asm("mov.b64 %0, {%1, %1};" : "=l"(wd[0]) : "f"(wcur.x));
            asm("mov.b64 %0, {%1, %1};" : "=l"(wd[1]) : "f"(wcur.y));
            asm("mov.b64 %0, {%1, %1};" : "=l"(wd[2]) : "f"(wcur.z));
            asm("mov.b64 %0, {%1, %1};" : "=l"(wd[3]) : "f"(wcur.w));

#pragma unroll
            for (int k = 0; k < 8; ++k) {
#pragma unroll
                for (int j = 0; j < 4; ++j) {
                    asm("fma.rn.f32x2 %0, %1, %2, %0;"
                        : "+l"(acc2[k][j]) : "l"(x2[k]), "l"(wd[j]));
                }
            }
        }

        // All lanes consumed slot s (LDS results already in registers);
        // safe for lane 0 to refill it with chunk c+2.
        __syncwarp();
        if (lane == 0 && c + NSTAGE < NCHUNK) {
            mbar_expect_tx(mbar0 + s * 8, WCHUNK_BYTES);
            bulk_g2s(wring + s * WCHUNK_BYTES,
                     wg + (size_t)(c + NSTAGE) * WCHUNK_BYTES,
                     WCHUNK_BYTES, mbar0 + s * 8);
        }
    }

    // ---------------- Phase 2: transpose through smem ----------------
    __syncthreads();   // done reading x tile (outs reuses x region only)
    // outs[c][b*128 + o], c = warp (0..3)
    float* outs = sm;
#pragma unroll
    for (int k = 0; k < 8; ++k) {
#pragma unroll
        for (int j = 0; j < 4; ++j) {
            float lo, hi;
            asm("mov.b64 {%0, %1}, %2;" : "=f"(lo), "=f"(hi) : "l"(acc2[k][j]));
            int o = 4 * lane + j;
            outs[warp * 2048 + (2 * k)     * 128 + o] = lo;
            outs[warp * 2048 + (2 * k + 1) * 128 + o] = hi;
        }
    }
    __syncthreads();

    // ---------------- Phase 3: coalesced global store ----------------
    // Each (b,o) pair p gets a 4-float d-contiguous run (one float4; the
    // adjacent-d0 CTA fills the sector's other half, merged in L2).
#pragma unroll
    for (int r = 0; r < 4; ++r) {
        int p4 = 4 * (tid + r * THREADS);   // groups of 4 consecutive p
        float v[D_TILE][4];
#pragma unroll
        for (int c = 0; c < D_TILE; ++c) {
            float4 t4 = *reinterpret_cast<float4*>(&outs[c * 2048 + p4]);
            v[c][0] = t4.x; v[c][1] = t4.y; v[c][2] = t4.z; v[c][3] = t4.w;
        }
#pragma unroll
        for (int pp = 0; pp < 4; ++pp) {
            int p = p4 + pp;            // p = b*128 + o
            float* op = out + (size_t)p * D_TOT + d0;
            *reinterpret_cast<float4*>(op) =
                make_float4(v[0][pp], v[1][pp], v[2][pp], v[3][pp]);
        }
    }
}

extern "C" void kernel_launch(void* const* d_in, const int* in_sizes, int n_in,
                              void* d_out, int out_size)
{
    (void)in_sizes; (void)n_in; (void)out_size;
    const float* x    = (const float*)d_in[0];
    const float* W    = (const float*)d_in[1];
    const float* bias = (const float*)d_in[2];
    float*       out  = (float*)d_out;

    // Idempotent, host-side, not a stream op: safe under graph capture.
    cudaFuncSetAttribute(grouped_linears_kernel,
                         cudaFuncAttributeMaxDynamicSharedMemorySize, SMEM_BYTES);

    grouped_linears_kernel<<<D_TOT / D_TILE, THREADS, SMEM_BYTES>>>(x, W, bias, out);
}

// round 13
// speedup vs baseline: 1.1529x; 1.0544x over previous
#include <cuda_runtime.h>
#include <cstdint>
#include <cstddef>

// GroupedLinearsAdvanced: out[b,o,d] = sum_i x[b,i,d] * W[d,i,o] + bias[d,o]
//   x:    [16, 128, 4096] fp32
//   W:    [4096, 128, 128] fp32   (256 MB, streamed once)
//   bias: [4096, 128] fp32
//   out:  [16, 128, 4096] fp32
//
// R12: two-kernel split. Six W-fetch variants all pinned DRAM at 37-46%;
// the shared culprit is the x/out access pattern (16B used per 16KB-strided
// row -> 32-line wavefronts per LDG, 2x sector amp, cross-CTA L1tex queue
// spread). Kernel 1 transposes x into scratch x_t[d][i*16+b] (coalesced
// both sides). Kernel 2 is the proven R5 core with phase 0 reduced to a
// verbatim contiguous 32KB copy. Inner f32x2 loop and output transpose
// unchanged from the 77.8us best.

#define B_SZ     16
#define IN_D     128
#define OUT_D    128
#define D_TOT    4096
#define D_TILE   4
#define THREADS  128
#define PF_DEPTH 4
#define QTOT     (B_SZ * IN_D)             // 2048
#define SMEM_FLOATS (D_TILE * QTOT)        // 8192 floats = 32768 B

// 32MB scratch: x_t[d][q], q = i*16 + b
__device__ float g_xt[(size_t)D_TOT * QTOT];

// ---------------------------------------------------------------------------
// Kernel 1: x[b][i][d] -> x_t[d][i*16+b], 32x32 tiled shuffle-transpose.
// grid (64, 128): blockIdx.x = q-tile (32 q's = 2 i's x 16 b), blockIdx.y = d-tile.
// ---------------------------------------------------------------------------
__global__ void __launch_bounds__(256)
transpose_x_kernel(const float* __restrict__ x)
{
    __shared__ float tile[32][33];
    const int i2 = blockIdx.x;          // q base = i2*32
    const int D  = blockIdx.y * 32;     // d base
    const int r    = threadIdx.x >> 5;  // 0..7
    const int lane = threadIdx.x & 31;

    // load: 32 q-rows, each 32 consecutive d (coalesced)
#pragma unroll
    for (int qq = r; qq < 32; qq += 8) {
        int q = i2 * 32 + qq;
        int b = q & 15;
        int i = q >> 4;                 // q = i*16 + b
        tile[qq][lane] = x[((size_t)b * IN_D + i) * D_TOT + D + lane];
    }
    __syncthreads();

    // store: 32 d-rows, each 32 consecutive q (coalesced)
#pragma unroll
    for (int dd = r; dd < 32; dd += 8) {
        g_xt[(size_t)(D + dd) * QTOT + i2 * 32 + lane] = tile[lane][dd];
    }
}

// ---------------------------------------------------------------------------
// Kernel 2: the R5 GEMM core; phase 0 is now a contiguous 32KB copy.
// ---------------------------------------------------------------------------
__global__ void __launch_bounds__(THREADS, 4)
grouped_linears_kernel(const float* __restrict__ W,
                       const float* __restrict__ bias,
                       float* __restrict__ out)
{
    __shared__ float sm[SMEM_FLOATS];   // phase 1: x tile [dd*2048 + i*16 + b]
                                        // phase 2: out transpose [dd*2048 + p]
    const int tid  = threadIdx.x;
    const int warp = tid >> 5;          // 0..3, one d-channel per warp
    const int lane = tid & 31;
    const int d0   = blockIdx.x * D_TILE;
    const int d    = d0 + warp;

    // W[d][i][4*lane] as float4; each i advances 128 floats = 32 float4.
    // Kick the prefetch off FIRST so W is in flight during x staging.
    const float4* wp = reinterpret_cast<const float4*>(W + (size_t)d * IN_D * OUT_D) + lane;
    float4 wbuf[PF_DEPTH];
#pragma unroll
    for (int s = 0; s < PF_DEPTH; ++s) wbuf[s] = __ldcs(wp + s * 32);

    // bias early too
    float4 bv = *reinterpret_cast<const float4*>(bias + (size_t)d * OUT_D + 4 * lane);

    // ---------------- Phase 0: contiguous copy of the x tile ----------------
    // x_t rows d0..d0+3 are adjacent -> one 32KB contiguous run. Streaming
    // (each row consumed by exactly one CTA), so evict-first.
    {
        const float4* g4 = reinterpret_cast<const float4*>(g_xt + (size_t)d0 * QTOT);
        float4* s4 = reinterpret_cast<float4*>(sm);
#pragma unroll
        for (int r = 0; r < 16; ++r)
            s4[tid + r * THREADS] = __ldcs(g4 + tid + r * THREADS);
    }
    __syncthreads();

    // ---------------- Phase 1: main GEMM loop ----------------
    // acc2[k][j]: packed f32x2 accumulator for (b=2k lo, b=2k+1 hi), o = 4*lane + j.
    unsigned long long acc2[8][4];
    {
        float bj[4] = {bv.x, bv.y, bv.z, bv.w};
#pragma unroll
        for (int j = 0; j < 4; ++j) {
            unsigned long long pk;
            asm("mov.b64 %0, {%1, %1};" : "=l"(pk) : "f"(bj[j]));
#pragma unroll
            for (int k = 0; k < 8; ++k) acc2[k][j] = pk;
        }
    }

#pragma unroll 4
    for (int i = 0; i < IN_D; ++i) {
        // consume slot, immediately re-fill it PF_DEPTH iterations ahead
        float4 wcur = wbuf[i & (PF_DEPTH - 1)];
        int ipf = i + PF_DEPTH;
        if (ipf < IN_D) wbuf[i & (PF_DEPTH - 1)] = __ldcs(wp + ipf * 32);

        // x pairs for this (i, d): 16 consecutive floats = 4x LDS.128 broadcast
        const double2* xr =
            reinterpret_cast<const double2*>(&sm[warp * QTOT + i * 16]);
        double2 a0 = xr[0], a1 = xr[1], a2 = xr[2], a3 = xr[3];
        unsigned long long x2[8];
        x2[0] = __double_as_longlong(a0.x); x2[1] = __double_as_longlong(a0.y);
        x2[2] = __double_as_longlong(a1.x); x2[3] = __double_as_longlong(a1.y);
        x2[4] = __double_as_longlong(a2.x); x2[5] = __double_as_longlong(a2.y);
        x2[6] = __double_as_longlong(a3.x); x2[7] = __double_as_longlong(a3.y);

        // duplicate W scalars into both f32x2 halves
        unsigned long long wd[4];
        asm("mov.b64 %0, {%1, %1};" : "=l"(wd[0]) : "f"(wcur.x));
        asm("mov.b64 %0, {%1, %1};" : "=l"(wd[1]) : "f"(wcur.y));
        asm("mov.b64 %0, {%1, %1};" : "=l"(wd[2]) : "f"(wcur.z));
        asm("mov.b64 %0, {%1, %1};" : "=l"(wd[3]) : "f"(wcur.w));

#pragma unroll
        for (int k = 0; k < 8; ++k) {
#pragma unroll
            for (int j = 0; j < 4; ++j) {
                asm("fma.rn.f32x2 %0, %1, %2, %0;"
                    : "+l"(acc2[k][j]) : "l"(x2[k]), "l"(wd[j]));
            }
        }
    }

    // ---------------- Phase 2: transpose through smem ----------------
    __syncthreads();   // done reading x tile
    // outs[c][b*128 + o], c = warp (0..3)
    float* outs = sm;
#pragma unroll
    for (int k = 0; k < 8; ++k) {
#pragma unroll
        for (int j = 0; j < 4; ++j) {
            float lo, hi;
            asm("mov.b64 {%0, %1}, %2;" : "=f"(lo), "=f"(hi) : "l"(acc2[k][j]));
            int o = 4 * lane + j;
            outs[warp * 2048 + (2 * k)     * 128 + o] = lo;
            outs[warp * 2048 + (2 * k + 1) * 128 + o] = hi;
        }
    }
    __syncthreads();

    // ---------------- Phase 3: coalesced global store ----------------
    // Each (b,o) pair p gets a 4-float d-contiguous run (one float4; the
    // adjacent-d0 CTA fills the sector's other half, merged in L2).
#pragma unroll
    for (int r = 0; r < 4; ++r) {
        int p4 = 4 * (tid + r * THREADS);   // groups of 4 consecutive p
        float v[D_TILE][4];
#pragma unroll
        for (int c = 0; c < D_TILE; ++c) {
            float4 t4 = *reinterpret_cast<float4*>(&outs[c * 2048 + p4]);
            v[c][0] = t4.x; v[c][1] = t4.y; v[c][2] = t4.z; v[c][3] = t4.w;
        }
#pragma unroll
        for (int pp = 0; pp < 4; ++pp) {
            int p = p4 + pp;            // p = b*128 + o
            float* op = out + (size_t)p * D_TOT + d0;
            *reinterpret_cast<float4*>(op) =
                make_float4(v[0][pp], v[1][pp], v[2][pp], v[3][pp]);
        }
    }
}

extern "C" void kernel_launch(void* const* d_in, const int* in_sizes, int n_in,
                              void* d_out, int out_size)
{
    (void)in_sizes; (void)n_in; (void)out_size;
    const float* x    = (const float*)d_in[0];
    const float* W    = (const float*)d_in[1];
    const float* bias = (const float*)d_in[2];
    float*       out  = (float*)d_out;

    dim3 tgrid(QTOT / 32, D_TOT / 32);   // (64, 128)
    transpose_x_kernel<<<tgrid, 256>>>(x);
    grouped_linears_kernel<<<D_TOT / D_TILE, THREADS>>>(W, bias, out);
}